// round 13
// baseline (speedup 1.0000x reference)
#include <cuda_runtime.h>
#include <cuda_fp16.h>
#include <cstdint>

using fp16 = __half;

// ---------------- problem constants ----------------
#define B_   1024
#define T_   100
#define D_   300
#define U_   512
#define C_   14
#define N4U  2048
#define K0P  320              // x K padded to multiple of 32
#define XLDA (T_ * K0P)       // row stride of padded-x buffer

// ---------------- device scratch ----------------
__device__ float g_h0[B_*U_], g_c0[B_*U_], g_h1[B_*U_], g_c1[B_*U_];
__device__ float g_z0[B_*N4U], g_z1[B_*N4U];
__device__ fp16 g_h0h[B_*U_], g_h1h[B_*U_];
__device__ fp16 g_xh[B_*T_*K0P];
__device__ fp16 g_w0h[N4U*K0P];
__device__ fp16 g_u0h[N4U*U_];
__device__ fp16 g_w1h[N4U*U_];
__device__ fp16 g_u1h[N4U*U_];
__device__ int  g_act[T_][B_];   // active (unmasked) batch rows per step
__device__ int  g_nact[T_];

// ---------------- PTX helpers (generic PTX, compute_103-safe) ----------------
__device__ __forceinline__ uint32_t smem_u32(const void* p) {
    uint32_t a;
    asm("{ .reg .u64 t; cvta.to.shared.u64 t, %1; cvt.u32.u64 %0, t; }" : "=r"(a) : "l"(p));
    return a;
}
__device__ __forceinline__ void cp16(uint32_t dst, const void* src) {
    asm volatile("cp.async.cg.shared.global [%0], [%1], 16;" :: "r"(dst), "l"(src) : "memory");
}
#define CP_COMMIT() asm volatile("cp.async.commit_group;" ::: "memory")
#define CP_WAIT(n)  asm volatile("cp.async.wait_group %0;" :: "n"(n) : "memory")

__device__ __forceinline__ void mma16816(float c[4], const uint32_t a[4], const uint32_t b[2]) {
    asm volatile(
        "mma.sync.aligned.m16n8k16.row.col.f32.f16.f16.f32 "
        "{%0,%1,%2,%3}, {%4,%5,%6,%7}, {%8,%9}, {%0,%1,%2,%3};"
        : "+f"(c[0]), "+f"(c[1]), "+f"(c[2]), "+f"(c[3])
        : "r"(a[0]), "r"(a[1]), "r"(a[2]), "r"(a[3]), "r"(b[0]), "r"(b[1]));
}
__device__ __forceinline__ void ldsm_x4(uint32_t r[4], uint32_t a) {
    asm volatile("ldmatrix.sync.aligned.m8n8.x4.shared.b16 {%0,%1,%2,%3}, [%4];"
        : "=r"(r[0]), "=r"(r[1]), "=r"(r[2]), "=r"(r[3]) : "r"(a));
}
__device__ __forceinline__ void ldsm_x2(uint32_t r[2], uint32_t a) {
    asm volatile("ldmatrix.sync.aligned.m8n8.x2.shared.b16 {%0,%1}, [%2];"
        : "=r"(r[0]), "=r"(r[1]) : "r"(a));
}

// ---------------- init ----------------
__global__ void init_states() {
    int i = blockIdx.x * blockDim.x + threadIdx.x;
    if (i < B_ * U_) {
        g_h0[i] = 0.f; g_c0[i] = 0.f; g_h1[i] = 0.f; g_c1[i] = 0.f;
        fp16 z = __float2half_rn(0.f);
        g_h0h[i] = z; g_h1h[i] = z;
    }
}

// build per-step active-row lists (one block of 1024 threads per t)
__global__ __launch_bounds__(1024)
void build_act(const int* __restrict__ mask) {
    const int t = blockIdx.x;
    const int b = threadIdx.x;
    __shared__ int scan[1024];
    const int m = (mask[(size_t)b * T_ + t] > 0) ? 1 : 0;
    scan[b] = m;
    __syncthreads();
    for (int off = 1; off < 1024; off <<= 1) {
        int v = (b >= off) ? scan[b - off] : 0;
        __syncthreads();
        scan[b] += v;
        __syncthreads();
    }
    if (m) g_act[t][scan[b] - 1] = b;
    if (b == 1023) g_nact[t] = scan[1023];
}

// x [B,T,D] -> padded fp16 [B,T,K0P]
__global__ void xsplit(const float* __restrict__ x) {
    long long i = (long long)blockIdx.x * blockDim.x + threadIdx.x;
    if (i >= (long long)B_ * T_ * K0P) return;
    int d = (int)(i % K0P);
    long long bt = i / K0P;
    float v = (d < D_) ? x[bt * D_ + d] : 0.f;
    g_xh[i] = __float2half_rn(v);
}

// transpose weights: W [K x 2048] -> fp16 [2048 x Kp] (K-major, zero-padded)
__global__ void wsplit(const float* __restrict__ W, int K, int Kp,
                       fp16* __restrict__ oh) {
    __shared__ float tile[32][33];
    int kb = blockIdx.y * 32, nb = blockIdx.x * 32;
    #pragma unroll
    for (int i = 0; i < 32; i += 8) {
        int kk = kb + threadIdx.y + i;
        tile[threadIdx.y + i][threadIdx.x] = (kk < K) ? W[(size_t)kk * N4U + nb + threadIdx.x] : 0.f;
    }
    __syncthreads();
    #pragma unroll
    for (int i = 0; i < 32; i += 8) {
        int nn = nb + threadIdx.y + i;
        int kk = kb + threadIdx.x;
        if (kk < Kp)
            oh[(size_t)nn * Kp + kk] = __float2half_rn(tile[threadIdx.x][threadIdx.y + i]);
    }
}

// ---------------- job descriptors ----------------
struct GemmJob {
    const fp16 *A0h; int lda0, nch0;
    const fp16 *B0h; int ldb0;
    const fp16 *A1h; int lda1, nch1;
    const fp16 *B1h; int ldb1;
    int t;                 // -1 = skip
    float* Z;
};
struct LnJob {
    const float* Z;
    const float *gam, *bet, *bias;
    int t;                 // -1 = skip
    float *h, *c;
    fp16 *hh;
};

// ---------------- gather dual GEMM body (single fp16 product, M-tile 128) ----------------
#define KC 32
#define ROWB 80
#define A_TILE (128 * ROWB)             // 10240
#define B_TILE (128 * ROWB)             // 10240
#define STAGE_BYTES (A_TILE + B_TILE)   // 20480 : Ah, Bh
#define NSTAGE 3
#define GEMM_SMEM (NSTAGE * STAGE_BYTES)   // 61440

__device__ __forceinline__ void gemm_body(const GemmJob& j, int mtile, int ntile, char* sm)
{
    const int tid  = threadIdx.x;
    const int lane = tid & 31, wid = tid >> 5;
    const int wm = wid & 1, wn = wid >> 1;         // 2x4 warp grid, 64x32 per warp
    const int m0 = mtile * 128;
    const int n0 = ntile * 128;
    const uint32_t sbase = smem_u32(sm);
    const int nch = j.nch0 + j.nch1;
    const int nact = g_nact[j.t];
    if (m0 >= nact) return;
    const int* act = j.t >= 0 ? g_act[j.t] : nullptr;

    const int quad = tid & 3;
    const int lrow = tid >> 2;   // 0..63

    // gathered batch rows for this thread's two A-load rows (clamped for tail safety)
    const int gr0_l = m0 + lrow;
    const int gr1_l = m0 + lrow + 64;
    const int brow0 = act[gr0_l < nact ? gr0_l : (nact - 1)];
    const int brow1 = act[gr1_l < nact ? gr1_l : (nact - 1)];

    auto load_chunk = [&](int ch) {
        const fp16 *ah, *bh; int lda, ldb, k0;
        if (ch < j.nch0) { ah = j.A0h; bh = j.B0h; lda = j.lda0; ldb = j.ldb0; k0 = ch * KC; }
        else             { ah = j.A1h; bh = j.B1h; lda = j.lda1; ldb = j.ldb1; k0 = (ch - j.nch0) * KC; }
        const uint32_t sdst = sbase + (uint32_t)(ch % NSTAGE) * STAGE_BYTES;
        // A: 128 gathered rows x 64B
        {
            const size_t a0 = (size_t)brow0 * lda + k0 + quad * 8;
            const size_t a1 = (size_t)brow1 * lda + k0 + quad * 8;
            const uint32_t so0 = sdst + (uint32_t)(lrow * ROWB + quad * 16);
            cp16(so0,                         ah + a0);
            cp16(so0 + (uint32_t)(64 * ROWB), ah + a1);
        }
        // B: 128 rows x 64B
        #pragma unroll
        for (int half = 0; half < 2; ++half) {
            const int r = half * 64 + lrow;
            const size_t bo = (size_t)(n0 + r) * ldb + k0 + quad * 8;
            const uint32_t so = sdst + (uint32_t)(A_TILE + r * ROWB + quad * 16);
            cp16(so, bh + bo);
        }
        CP_COMMIT();
    };

    load_chunk(0);
    if (nch > 1) load_chunk(1);

    float acc[4][4][4];
    #pragma unroll
    for (int i = 0; i < 4; ++i)
        #pragma unroll
        for (int jj = 0; jj < 4; ++jj)
            #pragma unroll
            for (int k = 0; k < 4; ++k) acc[i][jj][k] = 0.f;

    const uint32_t aoff = (uint32_t)((lane & 15) * ROWB + ((lane >> 4) << 4));
    const uint32_t boff = (uint32_t)((lane & 7) * ROWB + (((lane >> 3) & 1) << 4));

    for (int ch = 0; ch < nch; ++ch) {
        if (ch + 1 < nch) { CP_WAIT(1); } else { CP_WAIT(0); }
        __syncthreads();
        if (ch + 2 < nch) load_chunk(ch + 2);

        const uint32_t stg = sbase + (uint32_t)(ch % NSTAGE) * STAGE_BYTES;
        const uint32_t sAh = stg;
        const uint32_t sBh = stg + A_TILE;

        #pragma unroll
        for (int kk = 0; kk < 2; ++kk) {
            const uint32_t kbase = (uint32_t)(kk * 32);
            uint32_t ah_[4][4], bhf[4][2];

            #pragma unroll
            for (int mf = 0; mf < 4; ++mf)
                ldsm_x4(ah_[mf], sAh + (uint32_t)((wm * 64 + mf * 16) * ROWB) + aoff + kbase);
            #pragma unroll
            for (int nf = 0; nf < 4; ++nf)
                ldsm_x2(bhf[nf], sBh + (uint32_t)((wn * 32 + nf * 8) * ROWB) + boff + kbase);

            #pragma unroll
            for (int mf = 0; mf < 4; ++mf)
                #pragma unroll
                for (int nf = 0; nf < 4; ++nf)
                    mma16816(acc[mf][nf], ah_[mf], bhf[nf]);
        }
        __syncthreads();
    }

    // epilogue: scatter to Z[act_row]
    #pragma unroll
    for (int mf = 0; mf < 4; ++mf) {
        const int ml = wm * 64 + mf * 16 + (lane >> 2);
        const int gr0 = m0 + ml, gr1 = gr0 + 8;
        const int br0 = (gr0 < nact) ? act[gr0] : -1;
        const int br1 = (gr1 < nact) ? act[gr1] : -1;
        #pragma unroll
        for (int nf = 0; nf < 4; ++nf) {
            const int n = n0 + wn * 32 + nf * 8 + (lane & 3) * 2;
            if (br0 >= 0)
                *(float2*)(j.Z + (size_t)br0 * N4U + n) = make_float2(acc[mf][nf][0], acc[mf][nf][1]);
            if (br1 >= 0)
                *(float2*)(j.Z + (size_t)br1 * N4U + n) = make_float2(acc[mf][nf][2], acc[mf][nf][3]);
        }
    }
}

// combined GEMM launch: y<8 -> job A, y>=8 -> job B (independent GEMMs)
__global__ __launch_bounds__(256, 2)
void comb_gemm(GemmJob ja, GemmJob jb)
{
    extern __shared__ __align__(128) char sm[];
    const int my = blockIdx.y;
    if (my < 8) { if (ja.t >= 0) gemm_body(ja, my,     blockIdx.x, sm); }
    else        { if (jb.t >= 0) gemm_body(jb, my - 8, blockIdx.x, sm); }
}

// ---------------- LN + gates for ONE row (block-collective, 256 threads) ----------------
__device__ __forceinline__ void ln_row(int b, const LnJob& j)
{
    const int tid = threadIdx.x;
    const int lane = tid & 31, warp = tid >> 5;
    __shared__ float red[8][4];
    __shared__ float mu[4], rstd[4];
    const float* zr = j.Z + (size_t)b * N4U;

    float v[4][2], s[4];
    #pragma unroll
    for (int g = 0; g < 4; ++g) {
        v[g][0] = zr[g*U_ + tid];
        v[g][1] = zr[g*U_ + tid + 256];
        s[g] = v[g][0] + v[g][1];
    }
    #pragma unroll
    for (int g = 0; g < 4; ++g)
        #pragma unroll
        for (int off = 16; off; off >>= 1)
            s[g] += __shfl_xor_sync(0xffffffffu, s[g], off);
    if (lane == 0) { red[warp][0]=s[0]; red[warp][1]=s[1]; red[warp][2]=s[2]; red[warp][3]=s[3]; }
    __syncthreads();
    if (tid < 4) {
        float tot = 0.f;
        #pragma unroll
        for (int w = 0; w < 8; ++w) tot += red[w][tid];
        mu[tid] = tot * (1.0f / U_);
    }
    __syncthreads();
    #pragma unroll
    for (int g = 0; g < 4; ++g) {
        float d0 = v[g][0]-mu[g], d1 = v[g][1]-mu[g];
        s[g] = d0*d0 + d1*d1;
        #pragma unroll
        for (int off = 16; off; off >>= 1)
            s[g] += __shfl_xor_sync(0xffffffffu, s[g], off);
    }
    if (lane == 0) { red[warp][0]=s[0]; red[warp][1]=s[1]; red[warp][2]=s[2]; red[warp][3]=s[3]; }
    __syncthreads();
    if (tid < 4) {
        float tot = 0.f;
        #pragma unroll
        for (int w = 0; w < 8; ++w) tot += red[w][tid];
        rstd[tid] = rsqrtf(tot * (1.0f / U_) + 1e-3f);
    }
    __syncthreads();

    #pragma unroll
    for (int r = 0; r < 2; ++r) {
        const int u = tid + r * 256;
        float n[4];
        #pragma unroll
        for (int g = 0; g < 4; ++g) {
            int idx = g*U_ + u;
            n[g] = j.gam[idx] * (v[g][r] - mu[g]) * rstd[g] + j.bet[idx] + j.bias[idx];
        }
        float ig = 1.f/(1.f+expf(-n[0]));
        float fg = 1.f/(1.f+expf(-n[1]));
        float cg = tanhf(n[2]);
        float og = 1.f/(1.f+expf(-n[3]));

        const size_t si = (size_t)b * U_ + u;
        float cn = fg * j.c[si] + ig * cg;
        float hn = og * tanhf(cn);
        j.c[si] = cn; j.h[si] = hn;
        j.hh[si] = __float2half_rn(hn);
    }
}

// combined LN launch: blocks [0,1024) -> job A, [1024,2048) -> job B
__global__ __launch_bounds__(256)
void comb_ln(LnJob ja, LnJob jb, const int* __restrict__ mask)
{
    const int idx = blockIdx.x;
    const LnJob& j = (idx < B_) ? ja : jb;
    if (j.t < 0) return;
    const int b = idx & (B_ - 1);
    if (mask[(size_t)b * T_ + j.t] == 0) return;
    ln_row(b, j);
}

// ---------------- dense head + softmax ----------------
__global__ __launch_bounds__(32)
void head(const float* __restrict__ h, const float* __restrict__ Wd,
          const float* __restrict__ bd, float* __restrict__ out)
{
    const int b = blockIdx.x, lane = threadIdx.x;
    float acc[C_];
    #pragma unroll
    for (int cc = 0; cc < C_; ++cc) acc[cc] = 0.f;
    for (int k = lane; k < U_; k += 32) {
        float hv = h[(size_t)b*U_ + k];
        const float* wr = Wd + (size_t)k*C_;
        #pragma unroll
        for (int cc = 0; cc < C_; ++cc) acc[cc] += hv * wr[cc];
    }
    #pragma unroll
    for (int cc = 0; cc < C_; ++cc)
        #pragma unroll
        for (int off = 16; off; off >>= 1)
            acc[cc] += __shfl_xor_sync(0xffffffffu, acc[cc], off);
    if (lane == 0) {
        float mx = -1e30f;
        #pragma unroll
        for (int cc = 0; cc < C_; ++cc) { acc[cc] += bd[cc]; mx = fmaxf(mx, acc[cc]); }
        float ss = 0.f;
        #pragma unroll
        for (int cc = 0; cc < C_; ++cc) { acc[cc] = expf(acc[cc]-mx); ss += acc[cc]; }
        float inv = 1.f/ss;
        #pragma unroll
        for (int cc = 0; cc < C_; ++cc) out[(size_t)b*C_ + cc] = acc[cc]*inv;
    }
}

// ---------------- launch ----------------
extern "C" void kernel_launch(void* const* d_in, const int* in_sizes, int n_in,
                              void* d_out, int out_size)
{
    const float* x    = (const float*)d_in[0];
    const int*   mask = (const int*)  d_in[1];
    const float* W0   = (const float*)d_in[2];
    const float* U0   = (const float*)d_in[3];
    const float* b0   = (const float*)d_in[4];
    const float* g0   = (const float*)d_in[5];
    const float* be0  = (const float*)d_in[6];
    const float* W1   = (const float*)d_in[7];
    const float* U1   = (const float*)d_in[8];
    const float* b1   = (const float*)d_in[9];
    const float* g1   = (const float*)d_in[10];
    const float* be1  = (const float*)d_in[11];
    const float* Wd   = (const float*)d_in[12];
    const float* bd   = (const float*)d_in[13];
    float* out = (float*)d_out;

    static bool attr_set = false;
    if (!attr_set) {
        cudaFuncSetAttribute(comb_gemm, cudaFuncAttributeMaxDynamicSharedMemorySize, GEMM_SMEM);
        attr_set = true;
    }

    float *h0, *c0, *h1, *c1, *z0p, *z1p;
    fp16 *h0h,*h1h,*xh,*w0h,*u0h,*w1h,*u1h;
    cudaGetSymbolAddress((void**)&h0, g_h0);  cudaGetSymbolAddress((void**)&c0, g_c0);
    cudaGetSymbolAddress((void**)&h1, g_h1);  cudaGetSymbolAddress((void**)&c1, g_c1);
    cudaGetSymbolAddress((void**)&z0p, g_z0); cudaGetSymbolAddress((void**)&z1p, g_z1);
    cudaGetSymbolAddress((void**)&h0h, g_h0h); cudaGetSymbolAddress((void**)&h1h, g_h1h);
    cudaGetSymbolAddress((void**)&xh, g_xh);
    cudaGetSymbolAddress((void**)&w0h, g_w0h); cudaGetSymbolAddress((void**)&u0h, g_u0h);
    cudaGetSymbolAddress((void**)&w1h, g_w1h); cudaGetSymbolAddress((void**)&u1h, g_u1h);

    init_states<<<(B_*U_ + 255)/256, 256>>>();
    build_act<<<T_, 1024>>>(mask);

    dim3 tb(32, 8);
    wsplit<<<dim3(N4U/32, K0P/32), tb>>>(W0, D_, K0P, w0h);
    wsplit<<<dim3(N4U/32, U_/32),  tb>>>(U0, U_, U_,  u0h);
    wsplit<<<dim3(N4U/32, U_/32),  tb>>>(W1, U_, U_,  w1h);
    wsplit<<<dim3(N4U/32, U_/32),  tb>>>(U1, U_, U_,  u1h);

    {
        long long tot = (long long)B_ * T_ * K0P;
        xsplit<<<(unsigned)((tot + 255)/256), 256>>>(x);
    }

    // job builders
    auto jg0 = [&](int t) {   // gemm0(t): Z0 = x_t@W0 + h0@U0
        GemmJob j;
        j.A0h = xh + (size_t)t*K0P; j.lda0 = XLDA; j.nch0 = K0P/KC;
        j.B0h = w0h; j.ldb0 = K0P;
        j.A1h = h0h; j.lda1 = U_; j.nch1 = U_/KC;
        j.B1h = u0h; j.ldb1 = U_;
        j.t = t; j.Z = z0p;
        return j;
    };
    auto jg1 = [&](int t) {   // gemm1(t): Z1 = h0@W1 + h1@U1
        GemmJob j;
        j.A0h = h0h; j.lda0 = U_; j.nch0 = U_/KC;
        j.B0h = w1h; j.ldb0 = U_;
        j.A1h = h1h; j.lda1 = U_; j.nch1 = U_/KC;
        j.B1h = u1h; j.ldb1 = U_;
        j.t = t; j.Z = z1p;
        return j;
    };
    auto jl0 = [&](int t) {
        LnJob j; j.Z = z0p; j.gam = g0; j.bet = be0; j.bias = b0; j.t = t;
        j.h = h0; j.c = c0; j.hh = h0h; return j;
    };
    auto jl1 = [&](int t) {
        LnJob j; j.Z = z1p; j.gam = g1; j.bet = be1; j.bias = b1; j.t = t;
        j.h = h1; j.c = c1; j.hh = h1h; return j;
    };
    GemmJob gskip = {}; gskip.t = -1;
    LnJob   lskip = {}; lskip.t = -1;

    const dim3 ggrid(N4U/128, 16);   // 16 x 16 (two jobs, 8 mtiles each)

    // prologue: gemm0(0), lngate0(0)
    comb_gemm<<<ggrid, 256, GEMM_SMEM>>>(gskip, jg0(0));
    comb_ln<<<2*B_, 256>>>(lskip, jl0(0), mask);

    // steady state: 2 launches per step
    for (int t = 0; t < T_ - 1; ++t) {
        comb_gemm<<<ggrid, 256, GEMM_SMEM>>>(jg1(t), jg0(t + 1));
        comb_ln<<<2*B_, 256>>>(jl1(t), jl0(t + 1), mask);
    }

    // epilogue: gemm1(99), lngate1(99), head
    comb_gemm<<<ggrid, 256, GEMM_SMEM>>>(jg1(T_ - 1), gskip);
    comb_ln<<<2*B_, 256>>>(jl1(T_ - 1), lskip, mask);
    head<<<B_, 32>>>(h1, Wd, bd, out);
}

// round 14
// speedup vs baseline: 1.1417x; 1.1417x over previous
#include <cuda_runtime.h>
#include <cuda_fp16.h>
#include <cstdint>

using fp16 = __half;

// ---------------- problem constants ----------------
#define B_   1024
#define T_   100
#define D_   300
#define U_   512
#define C_   14
#define N4U  2048
#define K0P  320              // x K padded to multiple of 32
#define XLDA (T_ * K0P)       // row stride of padded-x buffer

// ---------------- device scratch ----------------
__device__ float g_h0[B_*U_], g_c0[B_*U_], g_h1[B_*U_], g_c1[B_*U_];
__device__ float g_z0[B_*N4U], g_z1[B_*N4U];
__device__ fp16 g_h0h[B_*U_], g_h1h[B_*U_];
__device__ fp16 g_xh[B_*T_*K0P];
__device__ fp16 g_w0h[N4U*K0P];
__device__ fp16 g_u0h[N4U*U_];
__device__ fp16 g_w1h[N4U*U_];
__device__ fp16 g_u1h[N4U*U_];
__device__ int  g_act[T_][B_];   // active (unmasked) batch rows per step
__device__ int  g_nact[T_];

// ---------------- PTX helpers (generic PTX, compute_103-safe) ----------------
__device__ __forceinline__ uint32_t smem_u32(const void* p) {
    uint32_t a;
    asm("{ .reg .u64 t; cvta.to.shared.u64 t, %1; cvt.u32.u64 %0, t; }" : "=r"(a) : "l"(p));
    return a;
}
__device__ __forceinline__ void cp16(uint32_t dst, const void* src) {
    asm volatile("cp.async.cg.shared.global [%0], [%1], 16;" :: "r"(dst), "l"(src) : "memory");
}
#define CP_COMMIT() asm volatile("cp.async.commit_group;" ::: "memory")
#define CP_WAIT(n)  asm volatile("cp.async.wait_group %0;" :: "n"(n) : "memory")

__device__ __forceinline__ void mma16816(float c[4], const uint32_t a[4], const uint32_t b[2]) {
    asm volatile(
        "mma.sync.aligned.m16n8k16.row.col.f32.f16.f16.f32 "
        "{%0,%1,%2,%3}, {%4,%5,%6,%7}, {%8,%9}, {%0,%1,%2,%3};"
        : "+f"(c[0]), "+f"(c[1]), "+f"(c[2]), "+f"(c[3])
        : "r"(a[0]), "r"(a[1]), "r"(a[2]), "r"(a[3]), "r"(b[0]), "r"(b[1]));
}
__device__ __forceinline__ void ldsm_x4(uint32_t r[4], uint32_t a) {
    asm volatile("ldmatrix.sync.aligned.m8n8.x4.shared.b16 {%0,%1,%2,%3}, [%4];"
        : "=r"(r[0]), "=r"(r[1]), "=r"(r[2]), "=r"(r[3]) : "r"(a));
}
__device__ __forceinline__ void ldsm_x2(uint32_t r[2], uint32_t a) {
    asm volatile("ldmatrix.sync.aligned.m8n8.x2.shared.b16 {%0,%1}, [%2];"
        : "=r"(r[0]), "=r"(r[1]) : "r"(a));
}

// ---------------- init ----------------
__global__ void init_states() {
    int i = blockIdx.x * blockDim.x + threadIdx.x;
    if (i < B_ * U_) {
        g_h0[i] = 0.f; g_c0[i] = 0.f; g_h1[i] = 0.f; g_c1[i] = 0.f;
        fp16 z = __float2half_rn(0.f);
        g_h0h[i] = z; g_h1h[i] = z;
    }
}

// build per-step active-row lists (one block of 1024 threads per t)
__global__ __launch_bounds__(1024)
void build_act(const int* __restrict__ mask) {
    const int t = blockIdx.x;
    const int b = threadIdx.x;
    __shared__ int scan[1024];
    const int m = (mask[(size_t)b * T_ + t] > 0) ? 1 : 0;
    scan[b] = m;
    __syncthreads();
    for (int off = 1; off < 1024; off <<= 1) {
        int v = (b >= off) ? scan[b - off] : 0;
        __syncthreads();
        scan[b] += v;
        __syncthreads();
    }
    if (m) g_act[t][scan[b] - 1] = b;
    if (b == 1023) g_nact[t] = scan[1023];
}

// x [B,T,D] -> padded fp16 [B,T,K0P]
__global__ void xsplit(const float* __restrict__ x) {
    long long i = (long long)blockIdx.x * blockDim.x + threadIdx.x;
    if (i >= (long long)B_ * T_ * K0P) return;
    int d = (int)(i % K0P);
    long long bt = i / K0P;
    float v = (d < D_) ? x[bt * D_ + d] : 0.f;
    g_xh[i] = __float2half_rn(v);
}

// transpose weights: W [K x 2048] -> fp16 [2048 x Kp] (K-major, zero-padded)
__global__ void wsplit(const float* __restrict__ W, int K, int Kp,
                       fp16* __restrict__ oh) {
    __shared__ float tile[32][33];
    int kb = blockIdx.y * 32, nb = blockIdx.x * 32;
    #pragma unroll
    for (int i = 0; i < 32; i += 8) {
        int kk = kb + threadIdx.y + i;
        tile[threadIdx.y + i][threadIdx.x] = (kk < K) ? W[(size_t)kk * N4U + nb + threadIdx.x] : 0.f;
    }
    __syncthreads();
    #pragma unroll
    for (int i = 0; i < 32; i += 8) {
        int nn = nb + threadIdx.y + i;
        int kk = kb + threadIdx.x;
        if (kk < Kp)
            oh[(size_t)nn * Kp + kk] = __float2half_rn(tile[threadIdx.x][threadIdx.y + i]);
    }
}

// ---------------- job descriptors ----------------
struct GemmJob {
    const fp16 *A0h; int lda0, nch0;
    const fp16 *B0h; int ldb0;
    const fp16 *A1h; int lda1, nch1;
    const fp16 *B1h; int ldb1;
    int t;                 // -1 = skip
    float* Z;
};
struct LnJob {
    const float* Z;
    const float *gam, *bet, *bias;
    int t;                 // -1 = skip
    float *h, *c;
    fp16 *hh;
};

// ---------------- gather dual GEMM body (single fp16 product, M-tile 128) ----------------
#define KC 32
#define ROWB 80
#define A_TILE (128 * ROWB)             // 10240
#define B_TILE (128 * ROWB)             // 10240
#define STAGE_BYTES (A_TILE + B_TILE)   // 20480 : Ah, Bh
#define NSTAGE 3
#define GEMM_SMEM (NSTAGE * STAGE_BYTES)   // 61440

__device__ __forceinline__ void gemm_body(const GemmJob& j, int mtile, int ntile, char* sm)
{
    const int tid  = threadIdx.x;
    const int lane = tid & 31, wid = tid >> 5;
    const int wm = wid & 1, wn = wid >> 1;         // 2x4 warp grid, 64x32 per warp
    const int m0 = mtile * 128;
    const int n0 = ntile * 128;
    const uint32_t sbase = smem_u32(sm);
    const int nch = j.nch0 + j.nch1;
    const int nact = g_nact[j.t];
    if (m0 >= nact) return;
    const int* act = g_act[j.t];

    const int quad = tid & 3;
    const int lrow = tid >> 2;   // 0..63

    // gathered batch rows for this thread's two A-load rows (clamped for tail safety)
    const int gr0_l = m0 + lrow;
    const int gr1_l = m0 + lrow + 64;
    const int brow0 = act[gr0_l < nact ? gr0_l : (nact - 1)];
    const int brow1 = act[gr1_l < nact ? gr1_l : (nact - 1)];

    auto load_chunk = [&](int ch) {
        const fp16 *ah, *bh; int lda, ldb, k0;
        if (ch < j.nch0) { ah = j.A0h; bh = j.B0h; lda = j.lda0; ldb = j.ldb0; k0 = ch * KC; }
        else             { ah = j.A1h; bh = j.B1h; lda = j.lda1; ldb = j.ldb1; k0 = (ch - j.nch0) * KC; }
        const uint32_t sdst = sbase + (uint32_t)(ch % NSTAGE) * STAGE_BYTES;
        // A: 128 gathered rows x 64B
        {
            const size_t a0 = (size_t)brow0 * lda + k0 + quad * 8;
            const size_t a1 = (size_t)brow1 * lda + k0 + quad * 8;
            const uint32_t so0 = sdst + (uint32_t)(lrow * ROWB + quad * 16);
            cp16(so0,                         ah + a0);
            cp16(so0 + (uint32_t)(64 * ROWB), ah + a1);
        }
        // B: 128 rows x 64B
        #pragma unroll
        for (int half = 0; half < 2; ++half) {
            const int r = half * 64 + lrow;
            const size_t bo = (size_t)(n0 + r) * ldb + k0 + quad * 8;
            const uint32_t so = sdst + (uint32_t)(A_TILE + r * ROWB + quad * 16);
            cp16(so, bh + bo);
        }
        CP_COMMIT();
    };

    load_chunk(0);
    if (nch > 1) load_chunk(1);

    float acc[4][4][4];
    #pragma unroll
    for (int i = 0; i < 4; ++i)
        #pragma unroll
        for (int jj = 0; jj < 4; ++jj)
            #pragma unroll
            for (int k = 0; k < 4; ++k) acc[i][jj][k] = 0.f;

    const uint32_t aoff = (uint32_t)((lane & 15) * ROWB + ((lane >> 4) << 4));
    const uint32_t boff = (uint32_t)((lane & 7) * ROWB + (((lane >> 3) & 1) << 4));

    for (int ch = 0; ch < nch; ++ch) {
        if (ch + 1 < nch) { CP_WAIT(1); } else { CP_WAIT(0); }
        __syncthreads();
        if (ch + 2 < nch) load_chunk(ch + 2);

        const uint32_t stg = sbase + (uint32_t)(ch % NSTAGE) * STAGE_BYTES;
        const uint32_t sAh = stg;
        const uint32_t sBh = stg + A_TILE;

        #pragma unroll
        for (int kk = 0; kk < 2; ++kk) {
            const uint32_t kbase = (uint32_t)(kk * 32);
            uint32_t ah_[4][4], bhf[4][2];

            #pragma unroll
            for (int mf = 0; mf < 4; ++mf)
                ldsm_x4(ah_[mf], sAh + (uint32_t)((wm * 64 + mf * 16) * ROWB) + aoff + kbase);
            #pragma unroll
            for (int nf = 0; nf < 4; ++nf)
                ldsm_x2(bhf[nf], sBh + (uint32_t)((wn * 32 + nf * 8) * ROWB) + boff + kbase);

            #pragma unroll
            for (int mf = 0; mf < 4; ++mf)
                #pragma unroll
                for (int nf = 0; nf < 4; ++nf)
                    mma16816(acc[mf][nf], ah_[mf], bhf[nf]);
        }
        __syncthreads();
    }

    // epilogue: scatter to Z[act_row]
    #pragma unroll
    for (int mf = 0; mf < 4; ++mf) {
        const int ml = wm * 64 + mf * 16 + (lane >> 2);
        const int gr0 = m0 + ml, gr1 = gr0 + 8;
        const int br0 = (gr0 < nact) ? act[gr0] : -1;
        const int br1 = (gr1 < nact) ? act[gr1] : -1;
        #pragma unroll
        for (int nf = 0; nf < 4; ++nf) {
            const int n = n0 + wn * 32 + nf * 8 + (lane & 3) * 2;
            if (br0 >= 0)
                *(float2*)(j.Z + (size_t)br0 * N4U + n) = make_float2(acc[mf][nf][0], acc[mf][nf][1]);
            if (br1 >= 0)
                *(float2*)(j.Z + (size_t)br1 * N4U + n) = make_float2(acc[mf][nf][2], acc[mf][nf][3]);
        }
    }
}

// combined GEMM launch: y<8 -> job A, y>=8 -> job B (independent GEMMs)
// occupancy 1: full register budget (no spills); ~128-160 working CTAs = one wave
__global__ __launch_bounds__(256, 1)
void comb_gemm(GemmJob ja, GemmJob jb)
{
    extern __shared__ __align__(128) char sm[];
    const int my = blockIdx.y;
    if (my < 8) { if (ja.t >= 0) gemm_body(ja, my,     blockIdx.x, sm); }
    else        { if (jb.t >= 0) gemm_body(jb, my - 8, blockIdx.x, sm); }
}

// ---------------- LN + gates for ONE row (block-collective, 256 threads) ----------------
__device__ __forceinline__ void ln_row(int b, const LnJob& j)
{
    const int tid = threadIdx.x;
    const int lane = tid & 31, warp = tid >> 5;
    __shared__ float red[8][4];
    __shared__ float mu[4], rstd[4];
    const float* zr = j.Z + (size_t)b * N4U;

    float v[4][2], s[4];
    #pragma unroll
    for (int g = 0; g < 4; ++g) {
        v[g][0] = zr[g*U_ + tid];
        v[g][1] = zr[g*U_ + tid + 256];
        s[g] = v[g][0] + v[g][1];
    }
    #pragma unroll
    for (int g = 0; g < 4; ++g)
        #pragma unroll
        for (int off = 16; off; off >>= 1)
            s[g] += __shfl_xor_sync(0xffffffffu, s[g], off);
    if (lane == 0) { red[warp][0]=s[0]; red[warp][1]=s[1]; red[warp][2]=s[2]; red[warp][3]=s[3]; }
    __syncthreads();
    if (tid < 4) {
        float tot = 0.f;
        #pragma unroll
        for (int w = 0; w < 8; ++w) tot += red[w][tid];
        mu[tid] = tot * (1.0f / U_);
    }
    __syncthreads();
    #pragma unroll
    for (int g = 0; g < 4; ++g) {
        float d0 = v[g][0]-mu[g], d1 = v[g][1]-mu[g];
        s[g] = d0*d0 + d1*d1;
        #pragma unroll
        for (int off = 16; off; off >>= 1)
            s[g] += __shfl_xor_sync(0xffffffffu, s[g], off);
    }
    if (lane == 0) { red[warp][0]=s[0]; red[warp][1]=s[1]; red[warp][2]=s[2]; red[warp][3]=s[3]; }
    __syncthreads();
    if (tid < 4) {
        float tot = 0.f;
        #pragma unroll
        for (int w = 0; w < 8; ++w) tot += red[w][tid];
        rstd[tid] = rsqrtf(tot * (1.0f / U_) + 1e-3f);
    }
    __syncthreads();

    #pragma unroll
    for (int r = 0; r < 2; ++r) {
        const int u = tid + r * 256;
        float n[4];
        #pragma unroll
        for (int g = 0; g < 4; ++g) {
            int idx = g*U_ + u;
            n[g] = j.gam[idx] * (v[g][r] - mu[g]) * rstd[g] + j.bet[idx] + j.bias[idx];
        }
        float ig = 1.f/(1.f+expf(-n[0]));
        float fg = 1.f/(1.f+expf(-n[1]));
        float cg = tanhf(n[2]);
        float og = 1.f/(1.f+expf(-n[3]));

        const size_t si = (size_t)b * U_ + u;
        float cn = fg * j.c[si] + ig * cg;
        float hn = og * tanhf(cn);
        j.c[si] = cn; j.h[si] = hn;
        j.hh[si] = __float2half_rn(hn);
    }
}

// combined LN launch: blocks [0,1024) -> job A, [1024,2048) -> job B
__global__ __launch_bounds__(256)
void comb_ln(LnJob ja, LnJob jb, const int* __restrict__ mask)
{
    const int idx = blockIdx.x;
    const LnJob& j = (idx < B_) ? ja : jb;
    if (j.t < 0) return;
    const int b = idx & (B_ - 1);
    if (mask[(size_t)b * T_ + j.t] == 0) return;
    ln_row(b, j);
}

// ---------------- dense head + softmax ----------------
__global__ __launch_bounds__(32)
void head(const float* __restrict__ h, const float* __restrict__ Wd,
          const float* __restrict__ bd, float* __restrict__ out)
{
    const int b = blockIdx.x, lane = threadIdx.x;
    float acc[C_];
    #pragma unroll
    for (int cc = 0; cc < C_; ++cc) acc[cc] = 0.f;
    for (int k = lane; k < U_; k += 32) {
        float hv = h[(size_t)b*U_ + k];
        const float* wr = Wd + (size_t)k*C_;
        #pragma unroll
        for (int cc = 0; cc < C_; ++cc) acc[cc] += hv * wr[cc];
    }
    #pragma unroll
    for (int cc = 0; cc < C_; ++cc)
        #pragma unroll
        for (int off = 16; off; off >>= 1)
            acc[cc] += __shfl_xor_sync(0xffffffffu, acc[cc], off);
    if (lane == 0) {
        float mx = -1e30f;
        #pragma unroll
        for (int cc = 0; cc < C_; ++cc) { acc[cc] += bd[cc]; mx = fmaxf(mx, acc[cc]); }
        float ss = 0.f;
        #pragma unroll
        for (int cc = 0; cc < C_; ++cc) { acc[cc] = expf(acc[cc]-mx); ss += acc[cc]; }
        float inv = 1.f/ss;
        #pragma unroll
        for (int cc = 0; cc < C_; ++cc) out[(size_t)b*C_ + cc] = acc[cc]*inv;
    }
}

// ---------------- launch ----------------
extern "C" void kernel_launch(void* const* d_in, const int* in_sizes, int n_in,
                              void* d_out, int out_size)
{
    const float* x    = (const float*)d_in[0];
    const int*   mask = (const int*)  d_in[1];
    const float* W0   = (const float*)d_in[2];
    const float* U0   = (const float*)d_in[3];
    const float* b0   = (const float*)d_in[4];
    const float* g0   = (const float*)d_in[5];
    const float* be0  = (const float*)d_in[6];
    const float* W1   = (const float*)d_in[7];
    const float* U1   = (const float*)d_in[8];
    const float* b1   = (const float*)d_in[9];
    const float* g1   = (const float*)d_in[10];
    const float* be1  = (const float*)d_in[11];
    const float* Wd   = (const float*)d_in[12];
    const float* bd   = (const float*)d_in[13];
    float* out = (float*)d_out;

    static bool attr_set = false;
    if (!attr_set) {
        cudaFuncSetAttribute(comb_gemm, cudaFuncAttributeMaxDynamicSharedMemorySize, GEMM_SMEM);
        attr_set = true;
    }

    float *h0, *c0, *h1, *c1, *z0p, *z1p;
    fp16 *h0h,*h1h,*xh,*w0h,*u0h,*w1h,*u1h;
    cudaGetSymbolAddress((void**)&h0, g_h0);  cudaGetSymbolAddress((void**)&c0, g_c0);
    cudaGetSymbolAddress((void**)&h1, g_h1);  cudaGetSymbolAddress((void**)&c1, g_c1);
    cudaGetSymbolAddress((void**)&z0p, g_z0); cudaGetSymbolAddress((void**)&z1p, g_z1);
    cudaGetSymbolAddress((void**)&h0h, g_h0h); cudaGetSymbolAddress((void**)&h1h, g_h1h);
    cudaGetSymbolAddress((void**)&xh, g_xh);
    cudaGetSymbolAddress((void**)&w0h, g_w0h); cudaGetSymbolAddress((void**)&u0h, g_u0h);
    cudaGetSymbolAddress((void**)&w1h, g_w1h); cudaGetSymbolAddress((void**)&u1h, g_u1h);

    init_states<<<(B_*U_ + 255)/256, 256>>>();
    build_act<<<T_, 1024>>>(mask);

    dim3 tb(32, 8);
    wsplit<<<dim3(N4U/32, K0P/32), tb>>>(W0, D_, K0P, w0h);
    wsplit<<<dim3(N4U/32, U_/32),  tb>>>(U0, U_, U_,  u0h);
    wsplit<<<dim3(N4U/32, U_/32),  tb>>>(W1, U_, U_,  w1h);
    wsplit<<<dim3(N4U/32, U_/32),  tb>>>(U1, U_, U_,  u1h);

    {
        long long tot = (long long)B_ * T_ * K0P;
        xsplit<<<(unsigned)((tot + 255)/256), 256>>>(x);
    }

    // job builders
    auto jg0 = [&](int t) {   // gemm0(t): Z0 = x_t@W0 + h0@U0
        GemmJob j;
        j.A0h = xh + (size_t)t*K0P; j.lda0 = XLDA; j.nch0 = K0P/KC;
        j.B0h = w0h; j.ldb0 = K0P;
        j.A1h = h0h; j.lda1 = U_; j.nch1 = U_/KC;
        j.B1h = u0h; j.ldb1 = U_;
        j.t = t; j.Z = z0p;
        return j;
    };
    auto jg1 = [&](int t) {   // gemm1(t): Z1 = h0@W1 + h1@U1
        GemmJob j;
        j.A0h = h0h; j.lda0 = U_; j.nch0 = U_/KC;
        j.B0h = w1h; j.ldb0 = U_;
        j.A1h = h1h; j.lda1 = U_; j.nch1 = U_/KC;
        j.B1h = u1h; j.ldb1 = U_;
        j.t = t; j.Z = z1p;
        return j;
    };
    auto jl0 = [&](int t) {
        LnJob j; j.Z = z0p; j.gam = g0; j.bet = be0; j.bias = b0; j.t = t;
        j.h = h0; j.c = c0; j.hh = h0h; return j;
    };
    auto jl1 = [&](int t) {
        LnJob j; j.Z = z1p; j.gam = g1; j.bet = be1; j.bias = b1; j.t = t;
        j.h = h1; j.c = c1; j.hh = h1h; return j;
    };
    GemmJob gskip = {}; gskip.t = -1;
    LnJob   lskip = {}; lskip.t = -1;

    const dim3 ggrid(N4U/128, 16);   // 16 x 16 (two jobs, 8 mtiles each)

    // prologue: gemm0(0), lngate0(0)
    comb_gemm<<<ggrid, 256, GEMM_SMEM>>>(gskip, jg0(0));
    comb_ln<<<2*B_, 256>>>(lskip, jl0(0), mask);

    // steady state: 2 launches per step
    for (int t = 0; t < T_ - 1; ++t) {
        comb_gemm<<<ggrid, 256, GEMM_SMEM>>>(jg1(t), jg0(t + 1));
        comb_ln<<<2*B_, 256>>>(jl1(t), jl0(t + 1), mask);
    }

    // epilogue: gemm1(99), lngate1(99), head
    comb_gemm<<<ggrid, 256, GEMM_SMEM>>>(jg1(T_ - 1), gskip);
    comb_ln<<<2*B_, 256>>>(jl1(T_ - 1), lskip, mask);
    head<<<B_, 32>>>(h1, Wd, bd, out);
}

// round 15
// speedup vs baseline: 1.4874x; 1.3028x over previous
#include <cuda_runtime.h>
#include <cuda_fp16.h>
#include <cstdint>

using fp16 = __half;

// ---------------- problem constants ----------------
#define B_   1024
#define T_   100
#define D_   300
#define U_   512
#define C_   14
#define N4U  2048
#define K0P  320              // x K padded to multiple of 64
#define XLDA (T_ * K0P)       // row stride of padded-x buffer

// ---------------- device scratch ----------------
__device__ float g_h0[B_*U_], g_c0[B_*U_], g_h1[B_*U_], g_c1[B_*U_];
__device__ float g_z0[B_*N4U], g_z1[B_*N4U];
__device__ fp16 g_h0h[B_*U_], g_h1h[B_*U_];
__device__ fp16 g_xh[B_*T_*K0P];
__device__ fp16 g_w0h[N4U*K0P];
__device__ fp16 g_u0h[N4U*U_];
__device__ fp16 g_w1h[N4U*U_];
__device__ fp16 g_u1h[N4U*U_];
__device__ int  g_act[T_][B_];   // active (unmasked) batch rows per step
__device__ int  g_nact[T_];

// ---------------- PTX helpers (generic PTX, compute_103-safe) ----------------
__device__ __forceinline__ uint32_t smem_u32(const void* p) {
    uint32_t a;
    asm("{ .reg .u64 t; cvta.to.shared.u64 t, %1; cvt.u32.u64 %0, t; }" : "=r"(a) : "l"(p));
    return a;
}
__device__ __forceinline__ void cp16(uint32_t dst, const void* src) {
    asm volatile("cp.async.cg.shared.global [%0], [%1], 16;" :: "r"(dst), "l"(src) : "memory");
}
#define CP_COMMIT() asm volatile("cp.async.commit_group;" ::: "memory")
#define CP_WAIT(n)  asm volatile("cp.async.wait_group %0;" :: "n"(n) : "memory")

__device__ __forceinline__ void mma16816(float c[4], const uint32_t a[4], const uint32_t b[2]) {
    asm volatile(
        "mma.sync.aligned.m16n8k16.row.col.f32.f16.f16.f32 "
        "{%0,%1,%2,%3}, {%4,%5,%6,%7}, {%8,%9}, {%0,%1,%2,%3};"
        : "+f"(c[0]), "+f"(c[1]), "+f"(c[2]), "+f"(c[3])
        : "r"(a[0]), "r"(a[1]), "r"(a[2]), "r"(a[3]), "r"(b[0]), "r"(b[1]));
}
__device__ __forceinline__ void ldsm_x4(uint32_t r[4], uint32_t a) {
    asm volatile("ldmatrix.sync.aligned.m8n8.x4.shared.b16 {%0,%1,%2,%3}, [%4];"
        : "=r"(r[0]), "=r"(r[1]), "=r"(r[2]), "=r"(r[3]) : "r"(a));
}
__device__ __forceinline__ void ldsm_x2(uint32_t r[2], uint32_t a) {
    asm volatile("ldmatrix.sync.aligned.m8n8.x2.shared.b16 {%0,%1}, [%2];"
        : "=r"(r[0]), "=r"(r[1]) : "r"(a));
}

// ---------------- init ----------------
__global__ void init_states() {
    int i = blockIdx.x * blockDim.x + threadIdx.x;
    if (i < B_ * U_) {
        g_h0[i] = 0.f; g_c0[i] = 0.f; g_h1[i] = 0.f; g_c1[i] = 0.f;
        fp16 z = __float2half_rn(0.f);
        g_h0h[i] = z; g_h1h[i] = z;
    }
}

// build per-step active-row lists (one block of 1024 threads per t)
__global__ __launch_bounds__(1024)
void build_act(const int* __restrict__ mask) {
    const int t = blockIdx.x;
    const int b = threadIdx.x;
    __shared__ int scan[1024];
    const int m = (mask[(size_t)b * T_ + t] > 0) ? 1 : 0;
    scan[b] = m;
    __syncthreads();
    for (int off = 1; off < 1024; off <<= 1) {
        int v = (b >= off) ? scan[b - off] : 0;
        __syncthreads();
        scan[b] += v;
        __syncthreads();
    }
    if (m) g_act[t][scan[b] - 1] = b;
    if (b == 1023) g_nact[t] = scan[1023];
}

// x [B,T,D] -> padded fp16 [B,T,K0P]
__global__ void xsplit(const float* __restrict__ x) {
    long long i = (long long)blockIdx.x * blockDim.x + threadIdx.x;
    if (i >= (long long)B_ * T_ * K0P) return;
    int d = (int)(i % K0P);
    long long bt = i / K0P;
    float v = (d < D_) ? x[bt * D_ + d] : 0.f;
    g_xh[i] = __float2half_rn(v);
}

// transpose weights: W [K x 2048] -> fp16 [2048 x Kp] (K-major, zero-padded)
__global__ void wsplit(const float* __restrict__ W, int K, int Kp,
                       fp16* __restrict__ oh) {
    __shared__ float tile[32][33];
    int kb = blockIdx.y * 32, nb = blockIdx.x * 32;
    #pragma unroll
    for (int i = 0; i < 32; i += 8) {
        int kk = kb + threadIdx.y + i;
        tile[threadIdx.y + i][threadIdx.x] = (kk < K) ? W[(size_t)kk * N4U + nb + threadIdx.x] : 0.f;
    }
    __syncthreads();
    #pragma unroll
    for (int i = 0; i < 32; i += 8) {
        int nn = nb + threadIdx.y + i;
        int kk = kb + threadIdx.x;
        if (kk < Kp)
            oh[(size_t)nn * Kp + kk] = __float2half_rn(tile[threadIdx.x][threadIdx.y + i]);
    }
}

// ---------------- job descriptors ----------------
struct GemmJob {
    const fp16 *A0h; int lda0, nch0;
    const fp16 *B0h; int ldb0;
    const fp16 *A1h; int lda1, nch1;
    const fp16 *B1h; int ldb1;
    int t;                 // -1 = skip
    float* Z;
};
struct LnJob {
    const float* Z;
    const float *gam, *bet, *bias;
    int t;                 // -1 = skip
    float *h, *c;
    fp16 *hh;
};

// ---------------- gather dual GEMM body (single fp16 product, M64/N128/K64) ----------------
#define KC 64
#define ROWB 144                        // 128 data + 16 pad (bank stride 4r mod 32: conflict-free)
#define A_TILE (64 * ROWB)              // 9216
#define B_TILE (128 * ROWB)             // 18432
#define STAGE_BYTES (A_TILE + B_TILE)   // 27648 : Ah, Bh
#define NSTAGE 3
#define GEMM_SMEM (NSTAGE * STAGE_BYTES)   // 82944

__device__ __forceinline__ void gemm_body(const GemmJob& j, int mtile, int ntile, char* sm)
{
    const int tid  = threadIdx.x;
    const int lane = tid & 31, wid = tid >> 5;
    const int wm = wid & 1, wn = wid >> 1;        // 2 x 4 warp grid (32 x 32 per warp)
    const int m0 = mtile * 64;
    const int n0 = ntile * 128;
    const uint32_t sbase = smem_u32(sm);
    const int nch = j.nch0 + j.nch1;
    const int nact = g_nact[j.t];
    if (m0 >= nact) return;
    const int* act = g_act[j.t];

    const int cg = tid & 7;      // 16B column group within 128B row
    const int lr = tid >> 3;     // 0..31

    // gathered batch rows for this thread's two A-load rows (clamped for tail safety)
    const int ga0 = m0 + lr, ga1 = m0 + lr + 32;
    const int browa0 = act[ga0 < nact ? ga0 : (nact - 1)];
    const int browa1 = act[ga1 < nact ? ga1 : (nact - 1)];

    auto load_chunk = [&](int ch) {
        const fp16 *ah, *bh; int lda, ldb, k0;
        if (ch < j.nch0) { ah = j.A0h; bh = j.B0h; lda = j.lda0; ldb = j.ldb0; k0 = ch * KC; }
        else             { ah = j.A1h; bh = j.B1h; lda = j.lda1; ldb = j.ldb1; k0 = (ch - j.nch0) * KC; }
        const uint32_t sdst = sbase + (uint32_t)(ch % NSTAGE) * STAGE_BYTES;
        // A: 64 gathered rows x 128B
        {
            const size_t a0 = (size_t)browa0 * lda + k0 + cg * 8;
            const size_t a1 = (size_t)browa1 * lda + k0 + cg * 8;
            const uint32_t so = sdst + (uint32_t)(lr * ROWB + cg * 16);
            cp16(so,                         ah + a0);
            cp16(so + (uint32_t)(32 * ROWB), ah + a1);
        }
        // B: 128 rows x 128B
        #pragma unroll
        for (int q = 0; q < 4; ++q) {
            const int r = q * 32 + lr;
            const size_t bo = (size_t)(n0 + r) * ldb + k0 + cg * 8;
            const uint32_t so = sdst + (uint32_t)(A_TILE + r * ROWB + cg * 16);
            cp16(so, bh + bo);
        }
        CP_COMMIT();
    };

    load_chunk(0);
    if (nch > 1) load_chunk(1);

    float acc[2][4][4];
    #pragma unroll
    for (int i = 0; i < 2; ++i)
        #pragma unroll
        for (int jj = 0; jj < 4; ++jj)
            #pragma unroll
            for (int k = 0; k < 4; ++k) acc[i][jj][k] = 0.f;

    const uint32_t aoff = (uint32_t)((lane & 15) * ROWB + ((lane >> 4) << 4));
    const uint32_t boff = (uint32_t)((lane & 7) * ROWB + (((lane >> 3) & 1) << 4));

    for (int ch = 0; ch < nch; ++ch) {
        if (ch + 1 < nch) { CP_WAIT(1); } else { CP_WAIT(0); }
        __syncthreads();
        if (ch + 2 < nch) load_chunk(ch + 2);

        const uint32_t stg = sbase + (uint32_t)(ch % NSTAGE) * STAGE_BYTES;
        const uint32_t sAh = stg;
        const uint32_t sBh = stg + A_TILE;

        #pragma unroll
        for (int kk = 0; kk < 4; ++kk) {
            const uint32_t kbase = (uint32_t)(kk * 32);   // 16 fp16 = 32 bytes
            uint32_t ah_[2][4], bhf[4][2];

            #pragma unroll
            for (int mf = 0; mf < 2; ++mf)
                ldsm_x4(ah_[mf], sAh + (uint32_t)((wm * 32 + mf * 16) * ROWB) + aoff + kbase);
            #pragma unroll
            for (int nf = 0; nf < 4; ++nf)
                ldsm_x2(bhf[nf], sBh + (uint32_t)((wn * 32 + nf * 8) * ROWB) + boff + kbase);

            #pragma unroll
            for (int mf = 0; mf < 2; ++mf)
                #pragma unroll
                for (int nf = 0; nf < 4; ++nf)
                    mma16816(acc[mf][nf], ah_[mf], bhf[nf]);
        }
        __syncthreads();
    }

    // epilogue: scatter to Z[act_row]
    #pragma unroll
    for (int mf = 0; mf < 2; ++mf) {
        const int ml = wm * 32 + mf * 16 + (lane >> 2);
        const int gr0 = m0 + ml, gr1 = gr0 + 8;
        const int br0 = (gr0 < nact) ? act[gr0] : -1;
        const int br1 = (gr1 < nact) ? act[gr1] : -1;
        #pragma unroll
        for (int nf = 0; nf < 4; ++nf) {
            const int n = n0 + wn * 32 + nf * 8 + (lane & 3) * 2;
            if (br0 >= 0)
                *(float2*)(j.Z + (size_t)br0 * N4U + n) = make_float2(acc[mf][nf][0], acc[mf][nf][1]);
            if (br1 >= 0)
                *(float2*)(j.Z + (size_t)br1 * N4U + n) = make_float2(acc[mf][nf][2], acc[mf][nf][3]);
        }
    }
}

// combined GEMM launch: y<16 -> job A, y>=16 -> job B (independent GEMMs)
__global__ __launch_bounds__(256, 1)
void comb_gemm(GemmJob ja, GemmJob jb)
{
    extern __shared__ __align__(128) char sm[];
    const int my = blockIdx.y;
    if (my < 16) { if (ja.t >= 0) gemm_body(ja, my,      blockIdx.x, sm); }
    else         { if (jb.t >= 0) gemm_body(jb, my - 16, blockIdx.x, sm); }
}

// ---------------- LN + gates for ONE row (block-collective, 256 threads) ----------------
__device__ __forceinline__ void ln_row(int b, const LnJob& j)
{
    const int tid = threadIdx.x;
    const int lane = tid & 31, warp = tid >> 5;
    __shared__ float red[8][4];
    __shared__ float mu[4], rstd[4];
    const float* zr = j.Z + (size_t)b * N4U;

    float v[4][2], s[4];
    #pragma unroll
    for (int g = 0; g < 4; ++g) {
        v[g][0] = zr[g*U_ + tid];
        v[g][1] = zr[g*U_ + tid + 256];
        s[g] = v[g][0] + v[g][1];
    }
    #pragma unroll
    for (int g = 0; g < 4; ++g)
        #pragma unroll
        for (int off = 16; off; off >>= 1)
            s[g] += __shfl_xor_sync(0xffffffffu, s[g], off);
    if (lane == 0) { red[warp][0]=s[0]; red[warp][1]=s[1]; red[warp][2]=s[2]; red[warp][3]=s[3]; }
    __syncthreads();
    if (tid < 4) {
        float tot = 0.f;
        #pragma unroll
        for (int w = 0; w < 8; ++w) tot += red[w][tid];
        mu[tid] = tot * (1.0f / U_);
    }
    __syncthreads();
    #pragma unroll
    for (int g = 0; g < 4; ++g) {
        float d0 = v[g][0]-mu[g], d1 = v[g][1]-mu[g];
        s[g] = d0*d0 + d1*d1;
        #pragma unroll
        for (int off = 16; off; off >>= 1)
            s[g] += __shfl_xor_sync(0xffffffffu, s[g], off);
    }
    if (lane == 0) { red[warp][0]=s[0]; red[warp][1]=s[1]; red[warp][2]=s[2]; red[warp][3]=s[3]; }
    __syncthreads();
    if (tid < 4) {
        float tot = 0.f;
        #pragma unroll
        for (int w = 0; w < 8; ++w) tot += red[w][tid];
        rstd[tid] = rsqrtf(tot * (1.0f / U_) + 1e-3f);
    }
    __syncthreads();

    #pragma unroll
    for (int r = 0; r < 2; ++r) {
        const int u = tid + r * 256;
        float n[4];
        #pragma unroll
        for (int g = 0; g < 4; ++g) {
            int idx = g*U_ + u;
            n[g] = j.gam[idx] * (v[g][r] - mu[g]) * rstd[g] + j.bet[idx] + j.bias[idx];
        }
        float ig = 1.f/(1.f+expf(-n[0]));
        float fg = 1.f/(1.f+expf(-n[1]));
        float cg = tanhf(n[2]);
        float og = 1.f/(1.f+expf(-n[3]));

        const size_t si = (size_t)b * U_ + u;
        float cn = fg * j.c[si] + ig * cg;
        float hn = og * tanhf(cn);
        j.c[si] = cn; j.h[si] = hn;
        j.hh[si] = __float2half_rn(hn);
    }
}

// combined LN launch: blocks [0,1024) -> job A, [1024,2048) -> job B
__global__ __launch_bounds__(256)
void comb_ln(LnJob ja, LnJob jb, const int* __restrict__ mask)
{
    const int idx = blockIdx.x;
    const LnJob& j = (idx < B_) ? ja : jb;
    if (j.t < 0) return;
    const int b = idx & (B_ - 1);
    if (mask[(size_t)b * T_ + j.t] == 0) return;
    ln_row(b, j);
}

// ---------------- dense head + softmax ----------------
__global__ __launch_bounds__(32)
void head(const float* __restrict__ h, const float* __restrict__ Wd,
          const float* __restrict__ bd, float* __restrict__ out)
{
    const int b = blockIdx.x, lane = threadIdx.x;
    float acc[C_];
    #pragma unroll
    for (int cc = 0; cc < C_; ++cc) acc[cc] = 0.f;
    for (int k = lane; k < U_; k += 32) {
        float hv = h[(size_t)b*U_ + k];
        const float* wr = Wd + (size_t)k*C_;
        #pragma unroll
        for (int cc = 0; cc < C_; ++cc) acc[cc] += hv * wr[cc];
    }
    #pragma unroll
    for (int cc = 0; cc < C_; ++cc)
        #pragma unroll
        for (int off = 16; off; off >>= 1)
            acc[cc] += __shfl_xor_sync(0xffffffffu, acc[cc], off);
    if (lane == 0) {
        float mx = -1e30f;
        #pragma unroll
        for (int cc = 0; cc < C_; ++cc) { acc[cc] += bd[cc]; mx = fmaxf(mx, acc[cc]); }
        float ss = 0.f;
        #pragma unroll
        for (int cc = 0; cc < C_; ++cc) { acc[cc] = expf(acc[cc]-mx); ss += acc[cc]; }
        float inv = 1.f/ss;
        #pragma unroll
        for (int cc = 0; cc < C_; ++cc) out[(size_t)b*C_ + cc] = acc[cc]*inv;
    }
}

// ---------------- launch ----------------
extern "C" void kernel_launch(void* const* d_in, const int* in_sizes, int n_in,
                              void* d_out, int out_size)
{
    const float* x    = (const float*)d_in[0];
    const int*   mask = (const int*)  d_in[1];
    const float* W0   = (const float*)d_in[2];
    const float* U0   = (const float*)d_in[3];
    const float* b0   = (const float*)d_in[4];
    const float* g0   = (const float*)d_in[5];
    const float* be0  = (const float*)d_in[6];
    const float* W1   = (const float*)d_in[7];
    const float* U1   = (const float*)d_in[8];
    const float* b1   = (const float*)d_in[9];
    const float* g1   = (const float*)d_in[10];
    const float* be1  = (const float*)d_in[11];
    const float* Wd   = (const float*)d_in[12];
    const float* bd   = (const float*)d_in[13];
    float* out = (float*)d_out;

    static bool attr_set = false;
    if (!attr_set) {
        cudaFuncSetAttribute(comb_gemm, cudaFuncAttributeMaxDynamicSharedMemorySize, GEMM_SMEM);
        attr_set = true;
    }

    float *h0, *c0, *h1, *c1, *z0p, *z1p;
    fp16 *h0h,*h1h,*xh,*w0h,*u0h,*w1h,*u1h;
    cudaGetSymbolAddress((void**)&h0, g_h0);  cudaGetSymbolAddress((void**)&c0, g_c0);
    cudaGetSymbolAddress((void**)&h1, g_h1);  cudaGetSymbolAddress((void**)&c1, g_c1);
    cudaGetSymbolAddress((void**)&z0p, g_z0); cudaGetSymbolAddress((void**)&z1p, g_z1);
    cudaGetSymbolAddress((void**)&h0h, g_h0h); cudaGetSymbolAddress((void**)&h1h, g_h1h);
    cudaGetSymbolAddress((void**)&xh, g_xh);
    cudaGetSymbolAddress((void**)&w0h, g_w0h); cudaGetSymbolAddress((void**)&u0h, g_u0h);
    cudaGetSymbolAddress((void**)&w1h, g_w1h); cudaGetSymbolAddress((void**)&u1h, g_u1h);

    init_states<<<(B_*U_ + 255)/256, 256>>>();
    build_act<<<T_, 1024>>>(mask);

    dim3 tb(32, 8);
    wsplit<<<dim3(N4U/32, K0P/32), tb>>>(W0, D_, K0P, w0h);
    wsplit<<<dim3(N4U/32, U_/32),  tb>>>(U0, U_, U_,  u0h);
    wsplit<<<dim3(N4U/32, U_/32),  tb>>>(W1, U_, U_,  w1h);
    wsplit<<<dim3(N4U/32, U_/32),  tb>>>(U1, U_, U_,  u1h);

    {
        long long tot = (long long)B_ * T_ * K0P;
        xsplit<<<(unsigned)((tot + 255)/256), 256>>>(x);
    }

    // job builders
    auto jg0 = [&](int t) {   // gemm0(t): Z0 = x_t@W0 + h0@U0
        GemmJob j;
        j.A0h = xh + (size_t)t*K0P; j.lda0 = XLDA; j.nch0 = K0P/KC;
        j.B0h = w0h; j.ldb0 = K0P;
        j.A1h = h0h; j.lda1 = U_; j.nch1 = U_/KC;
        j.B1h = u0h; j.ldb1 = U_;
        j.t = t; j.Z = z0p;
        return j;
    };
    auto jg1 = [&](int t) {   // gemm1(t): Z1 = h0@W1 + h1@U1
        GemmJob j;
        j.A0h = h0h; j.lda0 = U_; j.nch0 = U_/KC;
        j.B0h = w1h; j.ldb0 = U_;
        j.A1h = h1h; j.lda1 = U_; j.nch1 = U_/KC;
        j.B1h = u1h; j.ldb1 = U_;
        j.t = t; j.Z = z1p;
        return j;
    };
    auto jl0 = [&](int t) {
        LnJob j; j.Z = z0p; j.gam = g0; j.bet = be0; j.bias = b0; j.t = t;
        j.h = h0; j.c = c0; j.hh = h0h; return j;
    };
    auto jl1 = [&](int t) {
        LnJob j; j.Z = z1p; j.gam = g1; j.bet = be1; j.bias = b1; j.t = t;
        j.h = h1; j.c = c1; j.hh = h1h; return j;
    };
    GemmJob gskip = {}; gskip.t = -1;
    LnJob   lskip = {}; lskip.t = -1;

    const dim3 ggrid(N4U/128, 32);   // 16 x 32 (two jobs, 16 mtiles each)

    // prologue: gemm0(0), lngate0(0)
    comb_gemm<<<ggrid, 256, GEMM_SMEM>>>(gskip, jg0(0));
    comb_ln<<<2*B_, 256>>>(lskip, jl0(0), mask);

    // steady state: 2 launches per step
    for (int t = 0; t < T_ - 1; ++t) {
        comb_gemm<<<ggrid, 256, GEMM_SMEM>>>(jg1(t), jg0(t + 1));
        comb_ln<<<2*B_, 256>>>(jl1(t), jl0(t + 1), mask);
    }

    // epilogue: gemm1(99), lngate1(99), head
    comb_gemm<<<ggrid, 256, GEMM_SMEM>>>(jg1(T_ - 1), gskip);
    comb_ln<<<2*B_, 256>>>(jl1(T_ - 1), lskip, mask);
    head<<<B_, 32>>>(h1, Wd, bd, out);
}